// round 12
// baseline (speedup 1.0000x reference)
#include <cuda_runtime.h>
#include <cuda_fp16.h>
#include <cstdint>

#define P_  8
#define B_  8
#define C_  128
#define L_  8192
#define PC  1024          // P*C
#define LS  4096          // L/2

// ---------------------------------------------------------------------------
// Static device scratch (no runtime allocation allowed)
// ---------------------------------------------------------------------------
__device__ __align__(16) __half g_D16[PC * PC];                   //  2 MB  W - I (fp16)
__device__ __align__(16) __half g_Xt [(long)B_ * LS * PC];        // 64 MB  sc^T [b][l][j] fp16
__device__ __align__(16) __half g_y16[(long)B_ * PC * LS];        // 64 MB  y    [b][j][l] fp16
__device__ float g_pS[PC * 256];   // per-channel partial sums   [j][slot]
__device__ float g_pQ[PC * 256];   // per-channel partial sumsq  [j][slot]
__device__ float g_mean[PC];
__device__ float g_rstd[PC];

__device__ __forceinline__ uint32_t smem_u32(const void* p) {
    uint32_t a;
    asm("{ .reg .u64 t; cvta.to.shared.u64 t, %1; cvt.u32.u64 %0, t; }" : "=r"(a) : "l"(p));
    return a;
}

#define CP_ASYNC16(saddr, gptr) \
    asm volatile("cp.async.cg.shared.global [%0], [%1], 16;" :: "r"(saddr), "l"(gptr))
#define CP_COMMIT() asm volatile("cp.async.commit_group;")
#define CP_WAIT1()  asm volatile("cp.async.wait_group 1;")

#define LDSM4(r0, r1, r2, r3, addr) \
    asm volatile("ldmatrix.sync.aligned.m8n8.x4.shared.b16 {%0,%1,%2,%3}, [%4];" \
        : "=r"(r0), "=r"(r1), "=r"(r2), "=r"(r3) : "r"(addr))

#define MMA16816(acc, a, b) \
    asm volatile("mma.sync.aligned.m16n8k16.row.col.f32.f16.f16.f32 " \
        "{%0,%1,%2,%3}, {%4,%5,%6,%7}, {%8,%9}, {%0,%1,%2,%3};" \
        : "+f"((acc)[0]), "+f"((acc)[1]), "+f"((acc)[2]), "+f"((acc)[3]) \
        : "r"((a)[0]), "r"((a)[1]), "r"((a)[2]), "r"((a)[3]), \
          "r"((b)[0]), "r"((b)[1]))

// ---------------------------------------------------------------------------
// Pass 1: Haar analysis (all 8 batches). Writes detail-half of output and
// fp16 sc transposed into g_Xt [b][l][j]. Staging pitch 66: low-conflict.
// ---------------------------------------------------------------------------
#define SHP 66

__global__ __launch_bounds__(256) void analysis_kernel(
    const float* __restrict__ xs, const float* __restrict__ A,
    const float* __restrict__ S, float* __restrict__ out)
{
    __shared__ __half sh[64 * SHP];        // [local l][local j]
    const int t  = threadIdx.x;
    const int b  = blockIdx.z;
    const int J0 = blockIdx.y * 64;
    const int M0 = blockIdx.x * 32;        // float4-group index (2 sc per group)

    const float a00 = A[0], a01 = A[1], a10 = A[2], a11 = A[3];
    const float s00 = S[0], s01 = S[1], s10 = S[2], s11 = S[3];

    const int m  = t & 31;
    const int jr = t >> 5;                 // 0..7
    #pragma unroll
    for (int jl = 0; jl < 8; jl++) {
        int jj = jr + 8 * jl;              // 0..63
        int j = J0 + jj;
        int p = j >> 7, c = j & 127;
        long base = ((long)((p * B_ + b) * C_ + c)) << 13;   // *8192
        float4 x4 = *(const float4*)(xs + base + 4 * (M0 + m));
        float sc0 = a00 * x4.x + a01 * x4.y;
        float sc1 = a00 * x4.z + a01 * x4.w;
        float d0  = a10 * x4.x + a11 * x4.y;
        float d1  = a10 * x4.z + a11 * x4.w;
        *(float2*)(out + base + LS + 2 * (M0 + m))
            = make_float2(s00 * d0 + s01 * d1, s10 * d0 + s11 * d1);
        sh[(2 * m) * SHP + jj]     = __float2half(sc0);
        sh[(2 * m + 1) * SHP + jj] = __float2half(sc1);
    }
    __syncthreads();
    const int q  = t & 31;                 // 2-half chunk (4B)
    const int r0 = t >> 5;                 // 0..7
    #pragma unroll
    for (int i = 0; i < 8; i++) {
        int r = r0 + 8 * i;                // local l row 0..63
        uint32_t v = *(const uint32_t*)&sh[r * SHP + 2 * q];
        *(uint32_t*)(g_Xt + ((long)(b * LS + 2 * M0 + r)) * PC + J0 + 2 * q) = v;
    }
}

// ---------------------------------------------------------------------------
// D = W - I in fp16 (identity handled exactly via the sc add-back)
// ---------------------------------------------------------------------------
__global__ void wsplit_kernel(const float* __restrict__ W)
{
    int i = blockIdx.x * 256 + threadIdx.x;
    int row = i >> 10, col = i & 1023;
    g_D16[i] = __float2half(W[i] - (row == col ? 1.0f : 0.0f));
}

// ---------------------------------------------------------------------------
// Pass 2: HMMA fp16 GEMM  y = sc + D@sc (K=1024), fp32 accumulate.
// CTA 256(M) x 128(N), 512 threads (4x4 warps of 64x32), 32 K-iters of BK=32,
// 3-stage cp.async pipeline (R9 schedule). 1 CTA/SM, 16 warps.
// Bigger CTA tile cuts cp.async store traffic/MAC by 25%.
// Epilogue: stage Xt block in smem, y16 = acc + sc^T, BN partials from fp32.
// ---------------------------------------------------------------------------
#define STAGE_B 24576          // A 16KB | B 8KB
#define GEMM_SMEM 79872        // max(3*24576=73728, epilogue 67584+4096*2+pad)

__device__ __forceinline__ void load_stage(uint32_t sbase, int stg,
    const __half* __restrict__ Asrc,
    const __half* __restrict__ Bsrc, int kk, int t)
{
    uint32_t sa = sbase + stg * STAGE_B;
    #pragma unroll
    for (int i = 0; i < 2; i++) {                     // A: 256 rows x 4 chunks
        int idx = t + 512 * i;
        int row = idx >> 2, c = idx & 3;
        uint32_t sw = (uint32_t)((c ^ ((row >> 1) & 3)) << 4);
        CP_ASYNC16(sa + row * 64 + sw, Asrc + (long)row * PC + kk * 32 + c * 8);
    }
    {                                                 // B: 128 rows x 4 chunks
        int row = t >> 2, c = t & 3;
        uint32_t sw = (uint32_t)((c ^ ((row >> 1) & 3)) << 4);
        CP_ASYNC16(sa + 16384 + row * 64 + sw, Bsrc + (long)row * PC + kk * 32 + c * 8);
    }
}

#define XP 264                 // epilogue staging pitch (halfs), 256 + 8

__global__ void __launch_bounds__(512, 1) gemm_kernel()
{
    extern __shared__ char smem[];
    const uint32_t sbase = smem_u32(smem);
    const int t    = threadIdx.x;
    const int lane = t & 31;
    const int wid  = t >> 5;              // 0..15
    const int wm   = wid >> 2;            // 0..3  (64 m-rows each)
    const int wn   = wid & 3;             // 0..3  (32 n-cols each)
    const int n0   = blockIdx.x * 128;
    const int m0   = blockIdx.y * 256;
    const int b    = blockIdx.z;

    const __half* Asrc = g_D16 + (long)m0 * PC;
    const __half* Bsrc = g_Xt + ((long)b * LS + n0) * PC;

    // per-lane ldmatrix constants
    const int rA  = lane & 15;
    const int hkA = lane >> 4;
    const int cA  = (rA >> 1) & 3;
    const uint32_t offA = (uint32_t)(wm * 64 + rA) * 64;
    const int rB  = (lane & 7) | ((lane >> 4) << 3);
    const int hkB = (lane >> 3) & 1;
    const int cB  = (rB >> 1) & 3;
    const uint32_t offB = 16384u + (uint32_t)(wn * 32 + rB) * 64;

    float acc[4][4][4];
    #pragma unroll
    for (int mi = 0; mi < 4; mi++)
        #pragma unroll
        for (int ni = 0; ni < 4; ni++)
            #pragma unroll
            for (int q = 0; q < 4; q++) acc[mi][ni][q] = 0.f;

    load_stage(sbase, 0, Asrc, Bsrc, 0, t); CP_COMMIT();
    load_stage(sbase, 1, Asrc, Bsrc, 1, t); CP_COMMIT();

    int stg = 0;
    for (int kt = 0; kt < 32; kt++) {
        CP_WAIT1();
        __syncthreads();
        {
            int kn = kt + 2;
            if (kn < 32) {
                int stn = stg + 2; if (stn >= 3) stn -= 3;
                load_stage(sbase, stn, Asrc, Bsrc, kn, t);
            }
            CP_COMMIT();
        }
        uint32_t sa = sbase + stg * STAGE_B;
        #pragma unroll
        for (int s2 = 0; s2 < 2; s2++) {
            uint32_t bf[4][2];
            #pragma unroll
            for (int p = 0; p < 2; p++) {
                uint32_t addr = sa + offB + p * (16 * 64)
                              + (uint32_t)(((2 * s2 + hkB) ^ cB) << 4);
                LDSM4(bf[2 * p][0], bf[2 * p][1], bf[2 * p + 1][0], bf[2 * p + 1][1], addr);
            }
            uint32_t a[4][4];
            #pragma unroll
            for (int mi = 0; mi < 4; mi++) {
                uint32_t addr = sa + offA + mi * (16 * 64)
                              + (uint32_t)(((2 * s2 + hkA) ^ cA) << 4);
                LDSM4(a[mi][0], a[mi][1], a[mi][2], a[mi][3], addr);
            }
            #pragma unroll
            for (int mi = 0; mi < 4; mi++)
                #pragma unroll
                for (int ni = 0; ni < 4; ni++)
                    MMA16816(acc[mi][ni], a[mi], bf[ni]);
        }
        if (++stg == 3) stg = 0;
    }

    // ---- Epilogue: stage Xt block (sc^T), y16 = acc + sc, BN partials ----
    __syncthreads();                       // pipeline stages -> scratch
    __half* sX = (__half*)smem;            // [l_local 128][j_local 256], pitch XP
    float* sS = (float*)(smem + 67584);    // [256][4]
    float* sQ = (float*)(smem + 67584 + 4096);

    #pragma unroll
    for (int i = 0; i < 8; i++) {          // 4096 uint4 chunks
        int idx = t + 512 * i;
        int row = idx >> 5, c = idx & 31;  // row 0..127, col chunk 0..31
        uint4 v = *(const uint4*)(g_Xt + ((long)(b * LS + n0 + row)) * PC + m0 + c * 8);
        *(uint4*)&sX[row * XP + c * 8] = v;
    }
    __syncthreads();

    const int rl = wm * 64 + (lane >> 2);  // local m-row base (0..255)
    const int cl0 = wn * 32 + (lane & 3) * 2;
    const int c0 = n0 + cl0;
    #pragma unroll
    for (int mi = 0; mi < 4; mi++) {
        int rla = rl + mi * 16, rlb = rla + 8;
        long oa = ((long)b * PC + m0 + rla) * LS + c0;
        long ob = ((long)b * PC + m0 + rlb) * LS + c0;
        float sa_ = 0.f, qa_ = 0.f, sb_ = 0.f, qb_ = 0.f;
        #pragma unroll
        for (int ni = 0; ni < 4; ni++) {
            int cl = cl0 + ni * 8;         // sX row (l-local), 0..127
            float y0 = acc[mi][ni][0] + __half2float(sX[cl * XP + rla]);
            float y1 = acc[mi][ni][1] + __half2float(sX[(cl + 1) * XP + rla]);
            float y2 = acc[mi][ni][2] + __half2float(sX[cl * XP + rlb]);
            float y3 = acc[mi][ni][3] + __half2float(sX[(cl + 1) * XP + rlb]);
            *(__half2*)(g_y16 + oa + ni * 8) = __floats2half2_rn(y0, y1);
            *(__half2*)(g_y16 + ob + ni * 8) = __floats2half2_rn(y2, y3);
            sa_ += y0 + y1; qa_ += y0 * y0 + y1 * y1;
            sb_ += y2 + y3; qb_ += y2 * y2 + y3 * y3;
        }
        sa_ += __shfl_xor_sync(0xffffffffu, sa_, 1);
        sa_ += __shfl_xor_sync(0xffffffffu, sa_, 2);
        qa_ += __shfl_xor_sync(0xffffffffu, qa_, 1);
        qa_ += __shfl_xor_sync(0xffffffffu, qa_, 2);
        sb_ += __shfl_xor_sync(0xffffffffu, sb_, 1);
        sb_ += __shfl_xor_sync(0xffffffffu, sb_, 2);
        qb_ += __shfl_xor_sync(0xffffffffu, qb_, 1);
        qb_ += __shfl_xor_sync(0xffffffffu, qb_, 2);
        if ((lane & 3) == 0) {
            sS[rla * 4 + wn] = sa_; sQ[rla * 4 + wn] = qa_;
            sS[rlb * 4 + wn] = sb_; sQ[rlb * 4 + wn] = qb_;
        }
    }
    __syncthreads();
    if (t < 256) {
        float s = sS[t * 4] + sS[t * 4 + 1] + sS[t * 4 + 2] + sS[t * 4 + 3];
        float q = sQ[t * 4] + sQ[t * 4 + 1] + sQ[t * 4 + 2] + sQ[t * 4 + 3];
        int slot = b * 32 + blockIdx.x;    // 256 slots per channel
        g_pS[(m0 + t) * 256 + slot] = s;
        g_pQ[(m0 + t) * 256 + slot] = q;
    }
}

// ---------------------------------------------------------------------------
// Pass 3: BN finalize — reduce 256 deterministic partials per channel.
// ---------------------------------------------------------------------------
__global__ void bn_finalize_kernel()
{
    int j = blockIdx.x;
    int t = threadIdx.x;                   // 256 threads
    float s = g_pS[j * 256 + t];
    float q = g_pQ[j * 256 + t];
    #pragma unroll
    for (int o = 16; o > 0; o >>= 1) {
        s += __shfl_down_sync(0xffffffffu, s, o);
        q += __shfl_down_sync(0xffffffffu, q, o);
    }
    __shared__ float ss[8], sq[8];
    int w = t >> 5;
    if ((t & 31) == 0) { ss[w] = s; sq[w] = q; }
    __syncthreads();
    if (t == 0) {
        float S = 0.f, Q = 0.f;
        #pragma unroll
        for (int i = 0; i < 8; i++) { S += ss[i]; Q += sq[i]; }
        const float inv = 1.f / (float)(B_ * LS);
        float mean = S * inv;
        float var  = Q * inv - mean * mean;
        g_mean[j] = mean;
        g_rstd[j] = rsqrtf(var + 1e-5f);
    }
}

// ---------------------------------------------------------------------------
// Pass 4: BN + exact GELU + Haar synthesis -> FIRST half of the output.
// ---------------------------------------------------------------------------
__device__ __forceinline__ float gelu_exact(float z)
{
    return 0.5f * z * (1.0f + erff(z * 0.70710678118654752440f));
}

__global__ __launch_bounds__(256) void synth_kernel(
    const float* __restrict__ S,
    const float* __restrict__ gamma,
    const float* __restrict__ beta,
    float* __restrict__ out)
{
    int tid = blockIdx.x * blockDim.x + threadIdx.x;   // < P*B*C*512
    int m8 = tid & 511;                  // group of 8 l-values
    int c  = (tid >> 9) & 127;
    int b  = (tid >> 16) & 7;
    int p  = tid >> 19;

    int j = p * C_ + c;
    const __half2* yp = (const __half2*)(g_y16 + ((long)(b * PC + j)) * LS + 8 * m8);
    uint4 raw = *(const uint4*)yp;
    float2 v0 = __half22float2(*(const __half2*)&raw.x);
    float2 v1 = __half22float2(*(const __half2*)&raw.y);
    float2 v2 = __half22float2(*(const __half2*)&raw.z);
    float2 v3 = __half22float2(*(const __half2*)&raw.w);

    float mean = g_mean[j], rstd = g_rstd[j];
    float gm = gamma[j] * rstd;
    float bo = beta[j] - mean * gm;
    float s00 = S[0], s01 = S[1], s10 = S[2], s11 = S[3];

    float a0 = gelu_exact(v0.x * gm + bo);
    float a1 = gelu_exact(v0.y * gm + bo);
    float a2 = gelu_exact(v1.x * gm + bo);
    float a3 = gelu_exact(v1.y * gm + bo);
    float a4 = gelu_exact(v2.x * gm + bo);
    float a5 = gelu_exact(v2.y * gm + bo);
    float a6 = gelu_exact(v3.x * gm + bo);
    float a7 = gelu_exact(v3.y * gm + bo);

    float4 o0 = make_float4(s00 * a0 + s01 * a1, s10 * a0 + s11 * a1,
                            s00 * a2 + s01 * a3, s10 * a2 + s11 * a3);
    float4 o1 = make_float4(s00 * a4 + s01 * a5, s10 * a4 + s11 * a5,
                            s00 * a6 + s01 * a7, s10 * a6 + s11 * a7);

    float* op = out + (((long)((p * B_ + b) * C_ + c)) << 13) + 8 * m8;
    *(float4*)op       = o0;
    *(float4*)(op + 4) = o1;
}

// ---------------------------------------------------------------------------
extern "C" void kernel_launch(void* const* d_in, const int* in_sizes, int n_in,
                              void* d_out, int out_size)
{
    const float* xs    = (const float*)d_in[0];
    const float* A     = (const float*)d_in[1];
    const float* S     = (const float*)d_in[2];
    const float* W     = (const float*)d_in[3];
    const float* gamma = (const float*)d_in[4];
    const float* beta  = (const float*)d_in[5];
    float* out = (float*)d_out;

    static int inited = 0;
    if (!inited) {
        cudaFuncSetAttribute(gemm_kernel,
                             cudaFuncAttributeMaxDynamicSharedMemorySize, GEMM_SMEM);
        inited = 1;
    }

    analysis_kernel<<<dim3(64, 16, 8), 256>>>(xs, A, S, out);
    wsplit_kernel<<<PC * PC / 256, 256>>>(W);
    gemm_kernel<<<dim3(32, 4, 8), 512, GEMM_SMEM>>>();
    bn_finalize_kernel<<<PC, 256>>>();
    synth_kernel<<<P_ * B_ * C_ * (LS / 8) / 256, 256>>>(S, gamma, beta, out);
}

// round 13
// speedup vs baseline: 1.1104x; 1.1104x over previous
#include <cuda_runtime.h>
#include <cuda_fp16.h>
#include <cstdint>

#define P_  8
#define B_  8
#define C_  128
#define L_  8192
#define PC  1024          // P*C
#define LS  4096          // L/2

// ---------------------------------------------------------------------------
// Static device scratch (no runtime allocation allowed)
// ---------------------------------------------------------------------------
__device__ __align__(16) __half g_D16[PC * PC];                   //  2 MB  W - I (fp16)
__device__ __align__(16) __half g_Xt [(long)B_ * LS * PC];        // 64 MB  sc^T [b][l][j] fp16
__device__ __align__(16) __half g_y16[(long)B_ * PC * LS];        // 64 MB  y    [b][j][l] fp16
__device__ float g_pS[PC * 256];   // per-channel partial sums   [j][slot]
__device__ float g_pQ[PC * 256];   // per-channel partial sumsq  [j][slot]
__device__ float g_mean[PC];
__device__ float g_rstd[PC];

__device__ __forceinline__ uint32_t smem_u32(const void* p) {
    uint32_t a;
    asm("{ .reg .u64 t; cvta.to.shared.u64 t, %1; cvt.u32.u64 %0, t; }" : "=r"(a) : "l"(p));
    return a;
}

#define CP_ASYNC16(saddr, gptr) \
    asm volatile("cp.async.cg.shared.global [%0], [%1], 16;" :: "r"(saddr), "l"(gptr))
#define CP_COMMIT() asm volatile("cp.async.commit_group;")
#define CP_WAIT1()  asm volatile("cp.async.wait_group 1;")

#define LDSM4(r0, r1, r2, r3, addr) \
    asm volatile("ldmatrix.sync.aligned.m8n8.x4.shared.b16 {%0,%1,%2,%3}, [%4];" \
        : "=r"(r0), "=r"(r1), "=r"(r2), "=r"(r3) : "r"(addr))

#define MMA16816(acc, a, b) \
    asm volatile("mma.sync.aligned.m16n8k16.row.col.f32.f16.f16.f32 " \
        "{%0,%1,%2,%3}, {%4,%5,%6,%7}, {%8,%9}, {%0,%1,%2,%3};" \
        : "+f"((acc)[0]), "+f"((acc)[1]), "+f"((acc)[2]), "+f"((acc)[3]) \
        : "r"((a)[0]), "r"((a)[1]), "r"((a)[2]), "r"((a)[3]), \
          "r"((b)[0]), "r"((b)[1]))

// ---------------------------------------------------------------------------
// Pass 1: Haar analysis (all 8 batches). Writes detail-half of output and
// fp16 sc transposed into g_Xt [b][l][j].
// Staging pitch 66 halfs: 2-way write conflicts (was 8-way), clean reads,
// coalesced 128B/warp Xt stores.
// ---------------------------------------------------------------------------
#define SHP 66

__global__ __launch_bounds__(256) void analysis_kernel(
    const float* __restrict__ xs, const float* __restrict__ A,
    const float* __restrict__ S, float* __restrict__ out)
{
    __shared__ __half sh[64 * SHP];        // [local l][local j]
    const int t  = threadIdx.x;
    const int b  = blockIdx.z;
    const int J0 = blockIdx.y * 64;
    const int M0 = blockIdx.x * 32;        // float4-group index (2 sc per group)

    const float a00 = A[0], a01 = A[1], a10 = A[2], a11 = A[3];
    const float s00 = S[0], s01 = S[1], s10 = S[2], s11 = S[3];

    const int m  = t & 31;
    const int jr = t >> 5;                 // 0..7
    #pragma unroll
    for (int jl = 0; jl < 8; jl++) {
        int jj = jr + 8 * jl;              // 0..63
        int j = J0 + jj;
        int p = j >> 7, c = j & 127;
        long base = ((long)((p * B_ + b) * C_ + c)) << 13;   // *8192
        float4 x4 = *(const float4*)(xs + base + 4 * (M0 + m));
        float sc0 = a00 * x4.x + a01 * x4.y;
        float sc1 = a00 * x4.z + a01 * x4.w;
        float d0  = a10 * x4.x + a11 * x4.y;
        float d1  = a10 * x4.z + a11 * x4.w;
        *(float2*)(out + base + LS + 2 * (M0 + m))
            = make_float2(s00 * d0 + s01 * d1, s10 * d0 + s11 * d1);
        sh[(2 * m) * SHP + jj]     = __float2half(sc0);
        sh[(2 * m + 1) * SHP + jj] = __float2half(sc1);
    }
    __syncthreads();
    const int q  = t & 31;                 // 2-half chunk (4B)
    const int r0 = t >> 5;                 // 0..7
    #pragma unroll
    for (int i = 0; i < 8; i++) {
        int r = r0 + 8 * i;                // local l row 0..63
        uint32_t v = *(const uint32_t*)&sh[r * SHP + 2 * q];
        *(uint32_t*)(g_Xt + ((long)(b * LS + 2 * M0 + r)) * PC + J0 + 2 * q) = v;
    }
}

// ---------------------------------------------------------------------------
// D = W - I in fp16 (identity handled exactly via the sc add-back)
// ---------------------------------------------------------------------------
__global__ void wsplit_kernel(const float* __restrict__ W)
{
    int i = blockIdx.x * 256 + threadIdx.x;
    int row = i >> 10, col = i & 1023;
    g_D16[i] = __float2half(W[i] - (row == col ? 1.0f : 0.0f));
}

// ---------------------------------------------------------------------------
// Pass 2: HMMA fp16 GEMM  y = sc + D@sc (K=1024), fp32 accumulate.
// EXACT R9 config: CTA 128(M) x 128(N), 256 threads (2x4 warps of 64x32),
// 32 K-iters of BK=32, 3-stage cp.async pipeline, __launch_bounds__(256,2).
// Epilogue: stage Xt block in smem, y16 = acc + sc^T, BN partials from fp32.
// ---------------------------------------------------------------------------
#define STAGE_B 16384          // A 8KB | B 8KB
#define GEMM_SMEM 73728        // max(3*STAGE_B=48K, epilogue 69632+4096)

__device__ __forceinline__ void load_stage(uint32_t sbase, int stg,
    const __half* __restrict__ Asrc,
    const __half* __restrict__ Bsrc, int kk, int t)
{
    uint32_t sa = sbase + stg * STAGE_B;
    #pragma unroll
    for (int i = 0; i < 2; i++) {                     // A: 128 rows x 4 chunks
        int idx = t + 256 * i;
        int row = idx >> 2, c = idx & 3;
        uint32_t sw = (uint32_t)((c ^ ((row >> 1) & 3)) << 4);
        CP_ASYNC16(sa + row * 64 + sw, Asrc + (long)row * PC + kk * 32 + c * 8);
    }
    #pragma unroll
    for (int i = 0; i < 2; i++) {                     // B: 128 rows x 4 chunks
        int idx = t + 256 * i;
        int row = idx >> 2, c = idx & 3;
        uint32_t sw = (uint32_t)((c ^ ((row >> 1) & 3)) << 4);
        CP_ASYNC16(sa + 8192 + row * 64 + sw, Bsrc + (long)row * PC + kk * 32 + c * 8);
    }
}

#define XP 136                 // staging pitch (halfs)

__global__ void __launch_bounds__(256, 2) gemm_kernel()
{
    extern __shared__ char smem[];
    const uint32_t sbase = smem_u32(smem);
    const int t    = threadIdx.x;
    const int lane = t & 31;
    const int wid  = t >> 5;
    const int wm   = wid >> 2;            // 0..1  (64 m-rows each)
    const int wn   = wid & 3;             // 0..3  (32 n-cols each)
    const int n0   = blockIdx.x * 128;
    const int m0   = blockIdx.y * 128;
    const int b    = blockIdx.z;

    const __half* Asrc = g_D16 + (long)m0 * PC;
    const __half* Bsrc = g_Xt + ((long)b * LS + n0) * PC;

    // per-lane ldmatrix constants
    const int rA  = lane & 15;
    const int hkA = lane >> 4;
    const int cA  = (rA >> 1) & 3;
    const uint32_t offA = (uint32_t)(wm * 64 + rA) * 64;
    const int rB  = (lane & 7) | ((lane >> 4) << 3);
    const int hkB = (lane >> 3) & 1;
    const int cB  = (rB >> 1) & 3;
    const uint32_t offB = 8192u + (uint32_t)(wn * 32 + rB) * 64;

    float acc[4][4][4];
    #pragma unroll
    for (int mi = 0; mi < 4; mi++)
        #pragma unroll
        for (int ni = 0; ni < 4; ni++)
            #pragma unroll
            for (int q = 0; q < 4; q++) acc[mi][ni][q] = 0.f;

    load_stage(sbase, 0, Asrc, Bsrc, 0, t); CP_COMMIT();
    load_stage(sbase, 1, Asrc, Bsrc, 1, t); CP_COMMIT();

    int stg = 0;
    for (int kt = 0; kt < 32; kt++) {
        CP_WAIT1();
        __syncthreads();
        {
            int kn = kt + 2;
            if (kn < 32) {
                int stn = stg + 2; if (stn >= 3) stn -= 3;
                load_stage(sbase, stn, Asrc, Bsrc, kn, t);
            }
            CP_COMMIT();
        }
        uint32_t sa = sbase + stg * STAGE_B;
        #pragma unroll
        for (int s2 = 0; s2 < 2; s2++) {
            uint32_t bf[4][2];
            #pragma unroll
            for (int p = 0; p < 2; p++) {
                uint32_t addr = sa + offB + p * (16 * 64)
                              + (uint32_t)(((2 * s2 + hkB) ^ cB) << 4);
                LDSM4(bf[2 * p][0], bf[2 * p][1], bf[2 * p + 1][0], bf[2 * p + 1][1], addr);
            }
            uint32_t a[4][4];
            #pragma unroll
            for (int mi = 0; mi < 4; mi++) {
                uint32_t addr = sa + offA + mi * (16 * 64)
                              + (uint32_t)(((2 * s2 + hkA) ^ cA) << 4);
                LDSM4(a[mi][0], a[mi][1], a[mi][2], a[mi][3], addr);
            }
            #pragma unroll
            for (int mi = 0; mi < 4; mi++)
                #pragma unroll
                for (int ni = 0; ni < 4; ni++)
                    MMA16816(acc[mi][ni], a[mi], bf[ni]);
        }
        if (++stg == 3) stg = 0;
    }

    // ---- Epilogue: stage Xt block (sc^T), y16 = acc + sc, BN partials ----
    __syncthreads();                       // pipeline stages -> scratch
    __half* sX = (__half*)smem;            // [l_local 128][j_local], pitch XP
    float* sS = (float*)(smem + 69632);    // [128][4]
    float* sQ = (float*)(smem + 69632 + 2048);

    #pragma unroll
    for (int i = 0; i < 8; i++) {          // 2048 uint4 chunks
        int idx = t + 256 * i;
        int row = idx >> 4, c = idx & 15;
        uint4 v = *(const uint4*)(g_Xt + ((long)(b * LS + n0 + row)) * PC + m0 + c * 8);
        *(uint4*)&sX[row * XP + c * 8] = v;
    }
    __syncthreads();

    const int rl = wm * 64 + (lane >> 2);  // local m-row base
    const int cl0 = wn * 32 + (lane & 3) * 2;
    const int c0 = n0 + cl0;
    #pragma unroll
    for (int mi = 0; mi < 4; mi++) {
        int rla = rl + mi * 16, rlb = rla + 8;
        long oa = ((long)b * PC + m0 + rla) * LS + c0;
        long ob = ((long)b * PC + m0 + rlb) * LS + c0;
        float sa_ = 0.f, qa_ = 0.f, sb_ = 0.f, qb_ = 0.f;
        #pragma unroll
        for (int ni = 0; ni < 4; ni++) {
            int cl = cl0 + ni * 8;
            float y0 = acc[mi][ni][0] + __half2float(sX[cl * XP + rla]);
            float y1 = acc[mi][ni][1] + __half2float(sX[(cl + 1) * XP + rla]);
            float y2 = acc[mi][ni][2] + __half2float(sX[cl * XP + rlb]);
            float y3 = acc[mi][ni][3] + __half2float(sX[(cl + 1) * XP + rlb]);
            *(__half2*)(g_y16 + oa + ni * 8) = __floats2half2_rn(y0, y1);
            *(__half2*)(g_y16 + ob + ni * 8) = __floats2half2_rn(y2, y3);
            sa_ += y0 + y1; qa_ += y0 * y0 + y1 * y1;
            sb_ += y2 + y3; qb_ += y2 * y2 + y3 * y3;
        }
        sa_ += __shfl_xor_sync(0xffffffffu, sa_, 1);
        sa_ += __shfl_xor_sync(0xffffffffu, sa_, 2);
        qa_ += __shfl_xor_sync(0xffffffffu, qa_, 1);
        qa_ += __shfl_xor_sync(0xffffffffu, qa_, 2);
        sb_ += __shfl_xor_sync(0xffffffffu, sb_, 1);
        sb_ += __shfl_xor_sync(0xffffffffu, sb_, 2);
        qb_ += __shfl_xor_sync(0xffffffffu, qb_, 1);
        qb_ += __shfl_xor_sync(0xffffffffu, qb_, 2);
        if ((lane & 3) == 0) {
            sS[rla * 4 + wn] = sa_; sQ[rla * 4 + wn] = qa_;
            sS[rlb * 4 + wn] = sb_; sQ[rlb * 4 + wn] = qb_;
        }
    }
    __syncthreads();
    if (t < 128) {
        float s = sS[t * 4] + sS[t * 4 + 1] + sS[t * 4 + 2] + sS[t * 4 + 3];
        float q = sQ[t * 4] + sQ[t * 4 + 1] + sQ[t * 4 + 2] + sQ[t * 4 + 3];
        int slot = b * 32 + blockIdx.x;    // 256 slots per channel
        g_pS[(m0 + t) * 256 + slot] = s;
        g_pQ[(m0 + t) * 256 + slot] = q;
    }
}

// ---------------------------------------------------------------------------
// Pass 3: BN finalize — reduce 256 deterministic partials per channel.
// ---------------------------------------------------------------------------
__global__ void bn_finalize_kernel()
{
    int j = blockIdx.x;
    int t = threadIdx.x;                   // 256 threads
    float s = g_pS[j * 256 + t];
    float q = g_pQ[j * 256 + t];
    #pragma unroll
    for (int o = 16; o > 0; o >>= 1) {
        s += __shfl_down_sync(0xffffffffu, s, o);
        q += __shfl_down_sync(0xffffffffu, q, o);
    }
    __shared__ float ss[8], sq[8];
    int w = t >> 5;
    if ((t & 31) == 0) { ss[w] = s; sq[w] = q; }
    __syncthreads();
    if (t == 0) {
        float S = 0.f, Q = 0.f;
        #pragma unroll
        for (int i = 0; i < 8; i++) { S += ss[i]; Q += sq[i]; }
        const float inv = 1.f / (float)(B_ * LS);
        float mean = S * inv;
        float var  = Q * inv - mean * mean;
        g_mean[j] = mean;
        g_rstd[j] = rsqrtf(var + 1e-5f);
    }
}

// ---------------------------------------------------------------------------
// Pass 4: BN + exact GELU + Haar synthesis -> FIRST half of the output.
// ---------------------------------------------------------------------------
__device__ __forceinline__ float gelu_exact(float z)
{
    return 0.5f * z * (1.0f + erff(z * 0.70710678118654752440f));
}

__global__ __launch_bounds__(256) void synth_kernel(
    const float* __restrict__ S,
    const float* __restrict__ gamma,
    const float* __restrict__ beta,
    float* __restrict__ out)
{
    int tid = blockIdx.x * blockDim.x + threadIdx.x;   // < P*B*C*512
    int m8 = tid & 511;                  // group of 8 l-values
    int c  = (tid >> 9) & 127;
    int b  = (tid >> 16) & 7;
    int p  = tid >> 19;

    int j = p * C_ + c;
    const __half2* yp = (const __half2*)(g_y16 + ((long)(b * PC + j)) * LS + 8 * m8);
    uint4 raw = *(const uint4*)yp;
    float2 v0 = __half22float2(*(const __half2*)&raw.x);
    float2 v1 = __half22float2(*(const __half2*)&raw.y);
    float2 v2 = __half22float2(*(const __half2*)&raw.z);
    float2 v3 = __half22float2(*(const __half2*)&raw.w);

    float mean = g_mean[j], rstd = g_rstd[j];
    float gm = gamma[j] * rstd;
    float bo = beta[j] - mean * gm;
    float s00 = S[0], s01 = S[1], s10 = S[2], s11 = S[3];

    float a0 = gelu_exact(v0.x * gm + bo);
    float a1 = gelu_exact(v0.y * gm + bo);
    float a2 = gelu_exact(v1.x * gm + bo);
    float a3 = gelu_exact(v1.y * gm + bo);
    float a4 = gelu_exact(v2.x * gm + bo);
    float a5 = gelu_exact(v2.y * gm + bo);
    float a6 = gelu_exact(v3.x * gm + bo);
    float a7 = gelu_exact(v3.y * gm + bo);

    float4 o0 = make_float4(s00 * a0 + s01 * a1, s10 * a0 + s11 * a1,
                            s00 * a2 + s01 * a3, s10 * a2 + s11 * a3);
    float4 o1 = make_float4(s00 * a4 + s01 * a5, s10 * a4 + s11 * a5,
                            s00 * a6 + s01 * a7, s10 * a6 + s11 * a7);

    float* op = out + (((long)((p * B_ + b) * C_ + c)) << 13) + 8 * m8;
    *(float4*)op       = o0;
    *(float4*)(op + 4) = o1;
}

// ---------------------------------------------------------------------------
extern "C" void kernel_launch(void* const* d_in, const int* in_sizes, int n_in,
                              void* d_out, int out_size)
{
    const float* xs    = (const float*)d_in[0];
    const float* A     = (const float*)d_in[1];
    const float* S     = (const float*)d_in[2];
    const float* W     = (const float*)d_in[3];
    const float* gamma = (const float*)d_in[4];
    const float* beta  = (const float*)d_in[5];
    float* out = (float*)d_out;

    static int inited = 0;
    if (!inited) {
        cudaFuncSetAttribute(gemm_kernel,
                             cudaFuncAttributeMaxDynamicSharedMemorySize, GEMM_SMEM);
        inited = 1;
    }

    analysis_kernel<<<dim3(64, 16, 8), 256>>>(xs, A, S, out);
    wsplit_kernel<<<PC * PC / 256, 256>>>(W);
    gemm_kernel<<<dim3(32, 8, 8), 256, GEMM_SMEM>>>();
    bn_finalize_kernel<<<PC, 256>>>();
    synth_kernel<<<P_ * B_ * C_ * (LS / 8) / 256, 256>>>(S, gamma, beta, out);
}

// round 14
// speedup vs baseline: 1.1187x; 1.0074x over previous
#include <cuda_runtime.h>
#include <cuda_fp16.h>
#include <cstdint>

#define P_  8
#define B_  8
#define C_  128
#define L_  8192
#define PC  1024          // P*C
#define LS  4096          // L/2

// ---------------------------------------------------------------------------
// Static device scratch (no runtime allocation allowed)
// ---------------------------------------------------------------------------
__device__ __align__(16) __half g_D16[PC * PC];                   //  2 MB  W - I (fp16)
__device__ __align__(16) __half g_Xt [(long)B_ * LS * PC];        // 64 MB  sc^T [b][l][j] fp16
__device__ __align__(16) __half g_y16[(long)B_ * PC * LS];        // 64 MB  y    [b][j][l] fp16
__device__ float g_pS[PC * 256];   // per-channel partial sums   [j][slot]
__device__ float g_pQ[PC * 256];   // per-channel partial sumsq  [j][slot]
__device__ float g_mean[PC];
__device__ float g_rstd[PC];

__device__ __forceinline__ uint32_t smem_u32(const void* p) {
    uint32_t a;
    asm("{ .reg .u64 t; cvta.to.shared.u64 t, %1; cvt.u32.u64 %0, t; }" : "=r"(a) : "l"(p));
    return a;
}

#define CP_ASYNC16(saddr, gptr) \
    asm volatile("cp.async.cg.shared.global [%0], [%1], 16;" :: "r"(saddr), "l"(gptr))
#define CP_COMMIT() asm volatile("cp.async.commit_group;")
#define CP_WAIT1()  asm volatile("cp.async.wait_group 1;")

#define LDSM4(r0, r1, r2, r3, addr) \
    asm volatile("ldmatrix.sync.aligned.m8n8.x4.shared.b16 {%0,%1,%2,%3}, [%4];" \
        : "=r"(r0), "=r"(r1), "=r"(r2), "=r"(r3) : "r"(addr))

#define MMA16816(acc, a, b) \
    asm volatile("mma.sync.aligned.m16n8k16.row.col.f32.f16.f16.f32 " \
        "{%0,%1,%2,%3}, {%4,%5,%6,%7}, {%8,%9}, {%0,%1,%2,%3};" \
        : "+f"((acc)[0]), "+f"((acc)[1]), "+f"((acc)[2]), "+f"((acc)[3]) \
        : "r"((a)[0]), "r"((a)[1]), "r"((a)[2]), "r"((a)[3]), \
          "r"((b)[0]), "r"((b)[1]))

// ---------------------------------------------------------------------------
// Pass 1: Haar analysis (all 8 batches). Writes detail-half of output and
// fp16 sc transposed into g_Xt [b][l][j].
// R14: all 8 independent LDG.128s front-batched into registers (MLP 8)
// before any dependent compute/stores — hides the ~577cyc DRAM latency.
// ---------------------------------------------------------------------------
#define SHP 66

__global__ __launch_bounds__(256) void analysis_kernel(
    const float* __restrict__ xs, const float* __restrict__ A,
    const float* __restrict__ S, float* __restrict__ out)
{
    __shared__ __half sh[64 * SHP];        // [local l][local j]
    const int t  = threadIdx.x;
    const int b  = blockIdx.z;
    const int J0 = blockIdx.y * 64;
    const int M0 = blockIdx.x * 32;        // float4-group index (2 sc per group)

    const float a00 = A[0], a01 = A[1], a10 = A[2], a11 = A[3];
    const float s00 = S[0], s01 = S[1], s10 = S[2], s11 = S[3];

    const int m  = t & 31;
    const int jr = t >> 5;                 // 0..7

    // Phase 1: issue all 8 loads back-to-back (independent addresses)
    float4 x4v[8];
    #pragma unroll
    for (int jl = 0; jl < 8; jl++) {
        int jj = jr + 8 * jl;
        int j = J0 + jj;
        int p = j >> 7, c = j & 127;
        long base = ((long)((p * B_ + b) * C_ + c)) << 13;   // *8192
        x4v[jl] = *(const float4*)(xs + base + 4 * (M0 + m));
    }

    // Phase 2: compute, write detail-half of out, stage sc in smem
    #pragma unroll
    for (int jl = 0; jl < 8; jl++) {
        int jj = jr + 8 * jl;
        int j = J0 + jj;
        int p = j >> 7, c = j & 127;
        long base = ((long)((p * B_ + b) * C_ + c)) << 13;
        float4 x4 = x4v[jl];
        float sc0 = a00 * x4.x + a01 * x4.y;
        float sc1 = a00 * x4.z + a01 * x4.w;
        float d0  = a10 * x4.x + a11 * x4.y;
        float d1  = a10 * x4.z + a11 * x4.w;
        *(float2*)(out + base + LS + 2 * (M0 + m))
            = make_float2(s00 * d0 + s01 * d1, s10 * d0 + s11 * d1);
        sh[(2 * m) * SHP + jj]     = __float2half(sc0);
        sh[(2 * m + 1) * SHP + jj] = __float2half(sc1);
    }
    __syncthreads();
    const int q  = t & 31;                 // 2-half chunk (4B)
    const int r0 = t >> 5;                 // 0..7
    #pragma unroll
    for (int i = 0; i < 8; i++) {
        int r = r0 + 8 * i;                // local l row 0..63
        uint32_t v = *(const uint32_t*)&sh[r * SHP + 2 * q];
        *(uint32_t*)(g_Xt + ((long)(b * LS + 2 * M0 + r)) * PC + J0 + 2 * q) = v;
    }
}

// ---------------------------------------------------------------------------
// D = W - I in fp16 (identity handled exactly via the sc add-back)
// ---------------------------------------------------------------------------
__global__ void wsplit_kernel(const float* __restrict__ W)
{
    int i = blockIdx.x * 256 + threadIdx.x;
    int row = i >> 10, col = i & 1023;
    g_D16[i] = __float2half(W[i] - (row == col ? 1.0f : 0.0f));
}

// ---------------------------------------------------------------------------
// Pass 2: HMMA fp16 GEMM  y = sc + D@sc (K=1024), fp32 accumulate.
// EXACT R9 config: CTA 128(M) x 128(N), 256 threads (2x4 warps of 64x32),
// 32 K-iters of BK=32, 3-stage cp.async pipeline, __launch_bounds__(256,2).
// Epilogue: stage Xt block in smem, y16 = acc + sc^T, BN partials from fp32.
// ---------------------------------------------------------------------------
#define STAGE_B 16384          // A 8KB | B 8KB
#define GEMM_SMEM 73728        // max(3*STAGE_B=48K, epilogue 69632+4096)

__device__ __forceinline__ void load_stage(uint32_t sbase, int stg,
    const __half* __restrict__ Asrc,
    const __half* __restrict__ Bsrc, int kk, int t)
{
    uint32_t sa = sbase + stg * STAGE_B;
    #pragma unroll
    for (int i = 0; i < 2; i++) {                     // A: 128 rows x 4 chunks
        int idx = t + 256 * i;
        int row = idx >> 2, c = idx & 3;
        uint32_t sw = (uint32_t)((c ^ ((row >> 1) & 3)) << 4);
        CP_ASYNC16(sa + row * 64 + sw, Asrc + (long)row * PC + kk * 32 + c * 8);
    }
    #pragma unroll
    for (int i = 0; i < 2; i++) {                     // B: 128 rows x 4 chunks
        int idx = t + 256 * i;
        int row = idx >> 2, c = idx & 3;
        uint32_t sw = (uint32_t)((c ^ ((row >> 1) & 3)) << 4);
        CP_ASYNC16(sa + 8192 + row * 64 + sw, Bsrc + (long)row * PC + kk * 32 + c * 8);
    }
}

#define XP 136                 // staging pitch (halfs)

__global__ void __launch_bounds__(256, 2) gemm_kernel()
{
    extern __shared__ char smem[];
    const uint32_t sbase = smem_u32(smem);
    const int t    = threadIdx.x;
    const int lane = t & 31;
    const int wid  = t >> 5;
    const int wm   = wid >> 2;            // 0..1  (64 m-rows each)
    const int wn   = wid & 3;             // 0..3  (32 n-cols each)
    const int n0   = blockIdx.x * 128;
    const int m0   = blockIdx.y * 128;
    const int b    = blockIdx.z;

    const __half* Asrc = g_D16 + (long)m0 * PC;
    const __half* Bsrc = g_Xt + ((long)b * LS + n0) * PC;

    // per-lane ldmatrix constants
    const int rA  = lane & 15;
    const int hkA = lane >> 4;
    const int cA  = (rA >> 1) & 3;
    const uint32_t offA = (uint32_t)(wm * 64 + rA) * 64;
    const int rB  = (lane & 7) | ((lane >> 4) << 3);
    const int hkB = (lane >> 3) & 1;
    const int cB  = (rB >> 1) & 3;
    const uint32_t offB = 8192u + (uint32_t)(wn * 32 + rB) * 64;

    float acc[4][4][4];
    #pragma unroll
    for (int mi = 0; mi < 4; mi++)
        #pragma unroll
        for (int ni = 0; ni < 4; ni++)
            #pragma unroll
            for (int q = 0; q < 4; q++) acc[mi][ni][q] = 0.f;

    load_stage(sbase, 0, Asrc, Bsrc, 0, t); CP_COMMIT();
    load_stage(sbase, 1, Asrc, Bsrc, 1, t); CP_COMMIT();

    int stg = 0;
    for (int kt = 0; kt < 32; kt++) {
        CP_WAIT1();
        __syncthreads();
        {
            int kn = kt + 2;
            if (kn < 32) {
                int stn = stg + 2; if (stn >= 3) stn -= 3;
                load_stage(sbase, stn, Asrc, Bsrc, kn, t);
            }
            CP_COMMIT();
        }
        uint32_t sa = sbase + stg * STAGE_B;
        #pragma unroll
        for (int s2 = 0; s2 < 2; s2++) {
            uint32_t bf[4][2];
            #pragma unroll
            for (int p = 0; p < 2; p++) {
                uint32_t addr = sa + offB + p * (16 * 64)
                              + (uint32_t)(((2 * s2 + hkB) ^ cB) << 4);
                LDSM4(bf[2 * p][0], bf[2 * p][1], bf[2 * p + 1][0], bf[2 * p + 1][1], addr);
            }
            uint32_t a[4][4];
            #pragma unroll
            for (int mi = 0; mi < 4; mi++) {
                uint32_t addr = sa + offA + mi * (16 * 64)
                              + (uint32_t)(((2 * s2 + hkA) ^ cA) << 4);
                LDSM4(a[mi][0], a[mi][1], a[mi][2], a[mi][3], addr);
            }
            #pragma unroll
            for (int mi = 0; mi < 4; mi++)
                #pragma unroll
                for (int ni = 0; ni < 4; ni++)
                    MMA16816(acc[mi][ni], a[mi], bf[ni]);
        }
        if (++stg == 3) stg = 0;
    }

    // ---- Epilogue: stage Xt block (sc^T), y16 = acc + sc, BN partials ----
    __syncthreads();                       // pipeline stages -> scratch
    __half* sX = (__half*)smem;            // [l_local 128][j_local], pitch XP
    float* sS = (float*)(smem + 69632);    // [128][4]
    float* sQ = (float*)(smem + 69632 + 2048);

    #pragma unroll
    for (int i = 0; i < 8; i++) {          // 2048 uint4 chunks
        int idx = t + 256 * i;
        int row = idx >> 4, c = idx & 15;
        uint4 v = *(const uint4*)(g_Xt + ((long)(b * LS + n0 + row)) * PC + m0 + c * 8);
        *(uint4*)&sX[row * XP + c * 8] = v;
    }
    __syncthreads();

    const int rl = wm * 64 + (lane >> 2);  // local m-row base
    const int cl0 = wn * 32 + (lane & 3) * 2;
    const int c0 = n0 + cl0;
    #pragma unroll
    for (int mi = 0; mi < 4; mi++) {
        int rla = rl + mi * 16, rlb = rla + 8;
        long oa = ((long)b * PC + m0 + rla) * LS + c0;
        long ob = ((long)b * PC + m0 + rlb) * LS + c0;
        float sa_ = 0.f, qa_ = 0.f, sb_ = 0.f, qb_ = 0.f;
        #pragma unroll
        for (int ni = 0; ni < 4; ni++) {
            int cl = cl0 + ni * 8;
            float y0 = acc[mi][ni][0] + __half2float(sX[cl * XP + rla]);
            float y1 = acc[mi][ni][1] + __half2float(sX[(cl + 1) * XP + rla]);
            float y2 = acc[mi][ni][2] + __half2float(sX[cl * XP + rlb]);
            float y3 = acc[mi][ni][3] + __half2float(sX[(cl + 1) * XP + rlb]);
            *(__half2*)(g_y16 + oa + ni * 8) = __floats2half2_rn(y0, y1);
            *(__half2*)(g_y16 + ob + ni * 8) = __floats2half2_rn(y2, y3);
            sa_ += y0 + y1; qa_ += y0 * y0 + y1 * y1;
            sb_ += y2 + y3; qb_ += y2 * y2 + y3 * y3;
        }
        sa_ += __shfl_xor_sync(0xffffffffu, sa_, 1);
        sa_ += __shfl_xor_sync(0xffffffffu, sa_, 2);
        qa_ += __shfl_xor_sync(0xffffffffu, qa_, 1);
        qa_ += __shfl_xor_sync(0xffffffffu, qa_, 2);
        sb_ += __shfl_xor_sync(0xffffffffu, sb_, 1);
        sb_ += __shfl_xor_sync(0xffffffffu, sb_, 2);
        qb_ += __shfl_xor_sync(0xffffffffu, qb_, 1);
        qb_ += __shfl_xor_sync(0xffffffffu, qb_, 2);
        if ((lane & 3) == 0) {
            sS[rla * 4 + wn] = sa_; sQ[rla * 4 + wn] = qa_;
            sS[rlb * 4 + wn] = sb_; sQ[rlb * 4 + wn] = qb_;
        }
    }
    __syncthreads();
    if (t < 128) {
        float s = sS[t * 4] + sS[t * 4 + 1] + sS[t * 4 + 2] + sS[t * 4 + 3];
        float q = sQ[t * 4] + sQ[t * 4 + 1] + sQ[t * 4 + 2] + sQ[t * 4 + 3];
        int slot = b * 32 + blockIdx.x;    // 256 slots per channel
        g_pS[(m0 + t) * 256 + slot] = s;
        g_pQ[(m0 + t) * 256 + slot] = q;
    }
}

// ---------------------------------------------------------------------------
// Pass 3: BN finalize — reduce 256 deterministic partials per channel.
// ---------------------------------------------------------------------------
__global__ void bn_finalize_kernel()
{
    int j = blockIdx.x;
    int t = threadIdx.x;                   // 256 threads
    float s = g_pS[j * 256 + t];
    float q = g_pQ[j * 256 + t];
    #pragma unroll
    for (int o = 16; o > 0; o >>= 1) {
        s += __shfl_down_sync(0xffffffffu, s, o);
        q += __shfl_down_sync(0xffffffffu, q, o);
    }
    __shared__ float ss[8], sq[8];
    int w = t >> 5;
    if ((t & 31) == 0) { ss[w] = s; sq[w] = q; }
    __syncthreads();
    if (t == 0) {
        float S = 0.f, Q = 0.f;
        #pragma unroll
        for (int i = 0; i < 8; i++) { S += ss[i]; Q += sq[i]; }
        const float inv = 1.f / (float)(B_ * LS);
        float mean = S * inv;
        float var  = Q * inv - mean * mean;
        g_mean[j] = mean;
        g_rstd[j] = rsqrtf(var + 1e-5f);
    }
}

// ---------------------------------------------------------------------------
// Pass 4: BN + exact GELU + Haar synthesis -> FIRST half of the output.
// ---------------------------------------------------------------------------
__device__ __forceinline__ float gelu_exact(float z)
{
    return 0.5f * z * (1.0f + erff(z * 0.70710678118654752440f));
}

__global__ __launch_bounds__(256) void synth_kernel(
    const float* __restrict__ S,
    const float* __restrict__ gamma,
    const float* __restrict__ beta,
    float* __restrict__ out)
{
    int tid = blockIdx.x * blockDim.x + threadIdx.x;   // < P*B*C*512
    int m8 = tid & 511;                  // group of 8 l-values
    int c  = (tid >> 9) & 127;
    int b  = (tid >> 16) & 7;
    int p  = tid >> 19;

    int j = p * C_ + c;
    const __half2* yp = (const __half2*)(g_y16 + ((long)(b * PC + j)) * LS + 8 * m8);
    uint4 raw = *(const uint4*)yp;
    float2 v0 = __half22float2(*(const __half2*)&raw.x);
    float2 v1 = __half22float2(*(const __half2*)&raw.y);
    float2 v2 = __half22float2(*(const __half2*)&raw.z);
    float2 v3 = __half22float2(*(const __half2*)&raw.w);

    float mean = g_mean[j], rstd = g_rstd[j];
    float gm = gamma[j] * rstd;
    float bo = beta[j] - mean * gm;
    float s00 = S[0], s01 = S[1], s10 = S[2], s11 = S[3];

    float a0 = gelu_exact(v0.x * gm + bo);
    float a1 = gelu_exact(v0.y * gm + bo);
    float a2 = gelu_exact(v1.x * gm + bo);
    float a3 = gelu_exact(v1.y * gm + bo);
    float a4 = gelu_exact(v2.x * gm + bo);
    float a5 = gelu_exact(v2.y * gm + bo);
    float a6 = gelu_exact(v3.x * gm + bo);
    float a7 = gelu_exact(v3.y * gm + bo);

    float4 o0 = make_float4(s00 * a0 + s01 * a1, s10 * a0 + s11 * a1,
                            s00 * a2 + s01 * a3, s10 * a2 + s11 * a3);
    float4 o1 = make_float4(s00 * a4 + s01 * a5, s10 * a4 + s11 * a5,
                            s00 * a6 + s01 * a7, s10 * a6 + s11 * a7);

    float* op = out + (((long)((p * B_ + b) * C_ + c)) << 13) + 8 * m8;
    *(float4*)op       = o0;
    *(float4*)(op + 4) = o1;
}

// ---------------------------------------------------------------------------
extern "C" void kernel_launch(void* const* d_in, const int* in_sizes, int n_in,
                              void* d_out, int out_size)
{
    const float* xs    = (const float*)d_in[0];
    const float* A     = (const float*)d_in[1];
    const float* S     = (const float*)d_in[2];
    const float* W     = (const float*)d_in[3];
    const float* gamma = (const float*)d_in[4];
    const float* beta  = (const float*)d_in[5];
    float* out = (float*)d_out;

    static int inited = 0;
    if (!inited) {
        cudaFuncSetAttribute(gemm_kernel,
                             cudaFuncAttributeMaxDynamicSharedMemorySize, GEMM_SMEM);
        inited = 1;
    }

    analysis_kernel<<<dim3(64, 16, 8), 256>>>(xs, A, S, out);
    wsplit_kernel<<<PC * PC / 256, 256>>>(W);
    gemm_kernel<<<dim3(32, 8, 8), 256, GEMM_SMEM>>>();
    bn_finalize_kernel<<<PC, 256>>>();
    synth_kernel<<<P_ * B_ * C_ * (LS / 8) / 256, 256>>>(S, gamma, beta, out);
}

// round 15
// speedup vs baseline: 1.1327x; 1.0125x over previous
#include <cuda_runtime.h>
#include <cuda_fp16.h>
#include <cstdint>

#define P_  8
#define B_  8
#define C_  128
#define L_  8192
#define PC  1024          // P*C
#define LS  4096          // L/2

// ---------------------------------------------------------------------------
// Static device scratch (no runtime allocation allowed)
// ---------------------------------------------------------------------------
__device__ __align__(16) __half g_W16[PC * PC];                   //  2 MB  W (fp16)
__device__ __align__(16) __half g_Xt [(long)B_ * LS * PC];        // 64 MB  sc^T [b][l][j] fp16
__device__ __align__(16) __half g_y16[(long)B_ * PC * LS];        // 64 MB  y    [b][j][l] fp16
__device__ float g_pS[PC * 256];   // per-channel partial sums   [j][slot]
__device__ float g_pQ[PC * 256];   // per-channel partial sumsq  [j][slot]
__device__ float g_mean[PC];
__device__ float g_rstd[PC];

__device__ __forceinline__ uint32_t smem_u32(const void* p) {
    uint32_t a;
    asm("{ .reg .u64 t; cvta.to.shared.u64 t, %1; cvt.u32.u64 %0, t; }" : "=r"(a) : "l"(p));
    return a;
}

#define CP_ASYNC16(saddr, gptr) \
    asm volatile("cp.async.cg.shared.global [%0], [%1], 16;" :: "r"(saddr), "l"(gptr))
#define CP_COMMIT() asm volatile("cp.async.commit_group;")
#define CP_WAIT1()  asm volatile("cp.async.wait_group 1;")

#define LDSM4(r0, r1, r2, r3, addr) \
    asm volatile("ldmatrix.sync.aligned.m8n8.x4.shared.b16 {%0,%1,%2,%3}, [%4];" \
        : "=r"(r0), "=r"(r1), "=r"(r2), "=r"(r3) : "r"(addr))

#define MMA16816(acc, a, b) \
    asm volatile("mma.sync.aligned.m16n8k16.row.col.f32.f16.f16.f32 " \
        "{%0,%1,%2,%3}, {%4,%5,%6,%7}, {%8,%9}, {%0,%1,%2,%3};" \
        : "+f"((acc)[0]), "+f"((acc)[1]), "+f"((acc)[2]), "+f"((acc)[3]) \
        : "r"((a)[0]), "r"((a)[1]), "r"((a)[2]), "r"((a)[3]), \
          "r"((b)[0]), "r"((b)[1]))

// ---------------------------------------------------------------------------
// Pass 1 (half of 4 batches): Haar analysis. Writes detail-half of output and
// fp16 sc transposed into g_Xt [b][l][j]. MLP-8 front-batched loads.
// ---------------------------------------------------------------------------
#define SHP 66

__global__ __launch_bounds__(256) void analysis_kernel(
    const float* __restrict__ xs, const float* __restrict__ A,
    const float* __restrict__ S, float* __restrict__ out, int b0)
{
    __shared__ __half sh[64 * SHP];        // [local l][local j]
    const int t  = threadIdx.x;
    const int b  = b0 + blockIdx.z;
    const int J0 = blockIdx.y * 64;
    const int M0 = blockIdx.x * 32;        // float4-group index (2 sc per group)

    const float a00 = A[0], a01 = A[1], a10 = A[2], a11 = A[3];
    const float s00 = S[0], s01 = S[1], s10 = S[2], s11 = S[3];

    const int m  = t & 31;
    const int jr = t >> 5;                 // 0..7

    float4 x4v[8];
    #pragma unroll
    for (int jl = 0; jl < 8; jl++) {
        int jj = jr + 8 * jl;
        int j = J0 + jj;
        int p = j >> 7, c = j & 127;
        long base = ((long)((p * B_ + b) * C_ + c)) << 13;   // *8192
        x4v[jl] = *(const float4*)(xs + base + 4 * (M0 + m));
    }

    #pragma unroll
    for (int jl = 0; jl < 8; jl++) {
        int jj = jr + 8 * jl;
        int j = J0 + jj;
        int p = j >> 7, c = j & 127;
        long base = ((long)((p * B_ + b) * C_ + c)) << 13;
        float4 x4 = x4v[jl];
        float sc0 = a00 * x4.x + a01 * x4.y;
        float sc1 = a00 * x4.z + a01 * x4.w;
        float d0  = a10 * x4.x + a11 * x4.y;
        float d1  = a10 * x4.z + a11 * x4.w;
        *(float2*)(out + base + LS + 2 * (M0 + m))
            = make_float2(s00 * d0 + s01 * d1, s10 * d0 + s11 * d1);
        sh[(2 * m) * SHP + jj]     = __float2half(sc0);
        sh[(2 * m + 1) * SHP + jj] = __float2half(sc1);
    }
    __syncthreads();
    const int q  = t & 31;                 // 2-half chunk (4B)
    const int r0 = t >> 5;                 // 0..7
    #pragma unroll
    for (int i = 0; i < 8; i++) {
        int r = r0 + 8 * i;                // local l row 0..63
        uint32_t v = *(const uint32_t*)&sh[r * SHP + 2 * q];
        *(uint32_t*)(g_Xt + ((long)(b * LS + 2 * M0 + r)) * PC + J0 + 2 * q) = v;
    }
}

// ---------------------------------------------------------------------------
// W in fp16 (full matrix, no identity split)
// ---------------------------------------------------------------------------
__global__ void wsplit_kernel(const float* __restrict__ W)
{
    int i = blockIdx.x * 256 + threadIdx.x;
    g_W16[i] = __float2half(W[i]);
}

// ---------------------------------------------------------------------------
// Pass 2 (half of 4 batches): HMMA fp16 GEMM  y = W@sc (K=1024), fp32 accum.
// R9 config: CTA 128x128, 256 threads (2x4 warps of 64x32), 32 K-iters BK=32,
// 3-stage cp.async pipeline, __launch_bounds__(256,2).
// Simple epilogue: y16 = acc, BN partials from fp32 regs (no Xt re-read).
// ---------------------------------------------------------------------------
#define STAGE_B 16384          // A 8KB | B 8KB
#define GEMM_SMEM 49152        // 3 stages; epilogue reuses first 4KB

__device__ __forceinline__ void load_stage(uint32_t sbase, int stg,
    const __half* __restrict__ Asrc,
    const __half* __restrict__ Bsrc, int kk, int t)
{
    uint32_t sa = sbase + stg * STAGE_B;
    #pragma unroll
    for (int i = 0; i < 2; i++) {                     // A: 128 rows x 4 chunks
        int idx = t + 256 * i;
        int row = idx >> 2, c = idx & 3;
        uint32_t sw = (uint32_t)((c ^ ((row >> 1) & 3)) << 4);
        CP_ASYNC16(sa + row * 64 + sw, Asrc + (long)row * PC + kk * 32 + c * 8);
    }
    #pragma unroll
    for (int i = 0; i < 2; i++) {                     // B: 128 rows x 4 chunks
        int idx = t + 256 * i;
        int row = idx >> 2, c = idx & 3;
        uint32_t sw = (uint32_t)((c ^ ((row >> 1) & 3)) << 4);
        CP_ASYNC16(sa + 8192 + row * 64 + sw, Bsrc + (long)row * PC + kk * 32 + c * 8);
    }
}

__global__ void __launch_bounds__(256, 2) gemm_kernel(int b0)
{
    extern __shared__ char smem[];
    const uint32_t sbase = smem_u32(smem);
    const int t    = threadIdx.x;
    const int lane = t & 31;
    const int wid  = t >> 5;
    const int wm   = wid >> 2;            // 0..1  (64 m-rows each)
    const int wn   = wid & 3;             // 0..3  (32 n-cols each)
    const int n0   = blockIdx.x * 128;
    const int m0   = blockIdx.y * 128;
    const int b    = b0 + blockIdx.z;

    const __half* Asrc = g_W16 + (long)m0 * PC;
    const __half* Bsrc = g_Xt + ((long)b * LS + n0) * PC;

    // per-lane ldmatrix constants
    const int rA  = lane & 15;
    const int hkA = lane >> 4;
    const int cA  = (rA >> 1) & 3;
    const uint32_t offA = (uint32_t)(wm * 64 + rA) * 64;
    const int rB  = (lane & 7) | ((lane >> 4) << 3);
    const int hkB = (lane >> 3) & 1;
    const int cB  = (rB >> 1) & 3;
    const uint32_t offB = 8192u + (uint32_t)(wn * 32 + rB) * 64;

    float acc[4][4][4];
    #pragma unroll
    for (int mi = 0; mi < 4; mi++)
        #pragma unroll
        for (int ni = 0; ni < 4; ni++)
            #pragma unroll
            for (int q = 0; q < 4; q++) acc[mi][ni][q] = 0.f;

    load_stage(sbase, 0, Asrc, Bsrc, 0, t); CP_COMMIT();
    load_stage(sbase, 1, Asrc, Bsrc, 1, t); CP_COMMIT();

    int stg = 0;
    for (int kt = 0; kt < 32; kt++) {
        CP_WAIT1();
        __syncthreads();
        {
            int kn = kt + 2;
            if (kn < 32) {
                int stn = stg + 2; if (stn >= 3) stn -= 3;
                load_stage(sbase, stn, Asrc, Bsrc, kn, t);
            }
            CP_COMMIT();
        }
        uint32_t sa = sbase + stg * STAGE_B;
        #pragma unroll
        for (int s2 = 0; s2 < 2; s2++) {
            uint32_t bf[4][2];
            #pragma unroll
            for (int p = 0; p < 2; p++) {
                uint32_t addr = sa + offB + p * (16 * 64)
                              + (uint32_t)(((2 * s2 + hkB) ^ cB) << 4);
                LDSM4(bf[2 * p][0], bf[2 * p][1], bf[2 * p + 1][0], bf[2 * p + 1][1], addr);
            }
            uint32_t a[4][4];
            #pragma unroll
            for (int mi = 0; mi < 4; mi++) {
                uint32_t addr = sa + offA + mi * (16 * 64)
                              + (uint32_t)(((2 * s2 + hkA) ^ cA) << 4);
                LDSM4(a[mi][0], a[mi][1], a[mi][2], a[mi][3], addr);
            }
            #pragma unroll
            for (int mi = 0; mi < 4; mi++)
                #pragma unroll
                for (int ni = 0; ni < 4; ni++)
                    MMA16816(acc[mi][ni], a[mi], bf[ni]);
        }
        if (++stg == 3) stg = 0;
    }

    // ---- Epilogue: y16 = acc, BN partials from fp32 regs ----
    __syncthreads();                       // pipeline stages -> scratch
    float* sS = (float*)smem;              // [128][4]
    float* sQ = (float*)smem + 512;

    const int rl = wm * 64 + (lane >> 2);  // local m-row base
    const int c0 = n0 + wn * 32 + (lane & 3) * 2;
    #pragma unroll
    for (int mi = 0; mi < 4; mi++) {
        int rla = rl + mi * 16, rlb = rla + 8;
        long oa = ((long)b * PC + m0 + rla) * LS + c0;
        long ob = ((long)b * PC + m0 + rlb) * LS + c0;
        float sa_ = 0.f, qa_ = 0.f, sb_ = 0.f, qb_ = 0.f;
        #pragma unroll
        for (int ni = 0; ni < 4; ni++) {
            float y0 = acc[mi][ni][0], y1 = acc[mi][ni][1];
            float y2 = acc[mi][ni][2], y3 = acc[mi][ni][3];
            *(__half2*)(g_y16 + oa + ni * 8) = __floats2half2_rn(y0, y1);
            *(__half2*)(g_y16 + ob + ni * 8) = __floats2half2_rn(y2, y3);
            sa_ += y0 + y1; qa_ += y0 * y0 + y1 * y1;
            sb_ += y2 + y3; qb_ += y2 * y2 + y3 * y3;
        }
        sa_ += __shfl_xor_sync(0xffffffffu, sa_, 1);
        sa_ += __shfl_xor_sync(0xffffffffu, sa_, 2);
        qa_ += __shfl_xor_sync(0xffffffffu, qa_, 1);
        qa_ += __shfl_xor_sync(0xffffffffu, qa_, 2);
        sb_ += __shfl_xor_sync(0xffffffffu, sb_, 1);
        sb_ += __shfl_xor_sync(0xffffffffu, sb_, 2);
        qb_ += __shfl_xor_sync(0xffffffffu, qb_, 1);
        qb_ += __shfl_xor_sync(0xffffffffu, qb_, 2);
        if ((lane & 3) == 0) {
            sS[rla * 4 + wn] = sa_; sQ[rla * 4 + wn] = qa_;
            sS[rlb * 4 + wn] = sb_; sQ[rlb * 4 + wn] = qb_;
        }
    }
    __syncthreads();
    if (t < 128) {
        float s = sS[t * 4] + sS[t * 4 + 1] + sS[t * 4 + 2] + sS[t * 4 + 3];
        float q = sQ[t * 4] + sQ[t * 4 + 1] + sQ[t * 4 + 2] + sQ[t * 4 + 3];
        int slot = b * 32 + blockIdx.x;    // 256 slots per channel
        g_pS[(m0 + t) * 256 + slot] = s;
        g_pQ[(m0 + t) * 256 + slot] = q;
    }
}

// ---------------------------------------------------------------------------
// Pass 3: BN finalize — reduce 256 deterministic partials per channel.
// ---------------------------------------------------------------------------
__global__ void bn_finalize_kernel()
{
    int j = blockIdx.x;
    int t = threadIdx.x;                   // 256 threads
    float s = g_pS[j * 256 + t];
    float q = g_pQ[j * 256 + t];
    #pragma unroll
    for (int o = 16; o > 0; o >>= 1) {
        s += __shfl_down_sync(0xffffffffu, s, o);
        q += __shfl_down_sync(0xffffffffu, q, o);
    }
    __shared__ float ss[8], sq[8];
    int w = t >> 5;
    if ((t & 31) == 0) { ss[w] = s; sq[w] = q; }
    __syncthreads();
    if (t == 0) {
        float S = 0.f, Q = 0.f;
        #pragma unroll
        for (int i = 0; i < 8; i++) { S += ss[i]; Q += sq[i]; }
        const float inv = 1.f / (float)(B_ * LS);
        float mean = S * inv;
        float var  = Q * inv - mean * mean;
        g_mean[j] = mean;
        g_rstd[j] = rsqrtf(var + 1e-5f);
    }
}

// ---------------------------------------------------------------------------
// Pass 4: BN + exact GELU + Haar synthesis -> FIRST half of the output.
// ---------------------------------------------------------------------------
__device__ __forceinline__ float gelu_exact(float z)
{
    return 0.5f * z * (1.0f + erff(z * 0.70710678118654752440f));
}

__global__ __launch_bounds__(256) void synth_kernel(
    const float* __restrict__ S,
    const float* __restrict__ gamma,
    const float* __restrict__ beta,
    float* __restrict__ out)
{
    int tid = blockIdx.x * blockDim.x + threadIdx.x;   // < P*B*C*512
    int m8 = tid & 511;                  // group of 8 l-values
    int c  = (tid >> 9) & 127;
    int b  = (tid >> 16) & 7;
    int p  = tid >> 19;

    int j = p * C_ + c;
    const __half2* yp = (const __half2*)(g_y16 + ((long)(b * PC + j)) * LS + 8 * m8);
    uint4 raw = *(const uint4*)yp;
    float2 v0 = __half22float2(*(const __half2*)&raw.x);
    float2 v1 = __half22float2(*(const __half2*)&raw.y);
    float2 v2 = __half22float2(*(const __half2*)&raw.z);
    float2 v3 = __half22float2(*(const __half2*)&raw.w);

    float mean = g_mean[j], rstd = g_rstd[j];
    float gm = gamma[j] * rstd;
    float bo = beta[j] - mean * gm;
    float s00 = S[0], s01 = S[1], s10 = S[2], s11 = S[3];

    float a0 = gelu_exact(v0.x * gm + bo);
    float a1 = gelu_exact(v0.y * gm + bo);
    float a2 = gelu_exact(v1.x * gm + bo);
    float a3 = gelu_exact(v1.y * gm + bo);
    float a4 = gelu_exact(v2.x * gm + bo);
    float a5 = gelu_exact(v2.y * gm + bo);
    float a6 = gelu_exact(v3.x * gm + bo);
    float a7 = gelu_exact(v3.y * gm + bo);

    float4 o0 = make_float4(s00 * a0 + s01 * a1, s10 * a0 + s11 * a1,
                            s00 * a2 + s01 * a3, s10 * a2 + s11 * a3);
    float4 o1 = make_float4(s00 * a4 + s01 * a5, s10 * a4 + s11 * a5,
                            s00 * a6 + s01 * a7, s10 * a6 + s11 * a7);

    float* op = out + (((long)((p * B_ + b) * C_ + c)) << 13) + 8 * m8;
    *(float4*)op       = o0;
    *(float4*)(op + 4) = o1;
}

// ---------------------------------------------------------------------------
// Launch: two-half overlap — analysis halves on side stream; GEMM halves on
// main stream gated by events. A1 overlaps G0.
// ---------------------------------------------------------------------------
extern "C" void kernel_launch(void* const* d_in, const int* in_sizes, int n_in,
                              void* d_out, int out_size)
{
    const float* xs    = (const float*)d_in[0];
    const float* A     = (const float*)d_in[1];
    const float* S     = (const float*)d_in[2];
    const float* W     = (const float*)d_in[3];
    const float* gamma = (const float*)d_in[4];
    const float* beta  = (const float*)d_in[5];
    float* out = (float*)d_out;

    static int inited = 0;
    static cudaStream_t s2;
    static cudaEvent_t ev0, evA0, evA1;
    if (!inited) {
        cudaFuncSetAttribute(gemm_kernel,
                             cudaFuncAttributeMaxDynamicSharedMemorySize, GEMM_SMEM);
        cudaStreamCreateWithFlags(&s2, cudaStreamNonBlocking);
        cudaEventCreateWithFlags(&ev0,  cudaEventDisableTiming);
        cudaEventCreateWithFlags(&evA0, cudaEventDisableTiming);
        cudaEventCreateWithFlags(&evA1, cudaEventDisableTiming);
        inited = 1;
    }

    cudaEventRecord(ev0, 0);
    cudaStreamWaitEvent(s2, ev0, 0);

    wsplit_kernel<<<PC * PC / 256, 256>>>(W);

    analysis_kernel<<<dim3(64, 16, 4), 256, 0, s2>>>(xs, A, S, out, 0);
    cudaEventRecord(evA0, s2);
    analysis_kernel<<<dim3(64, 16, 4), 256, 0, s2>>>(xs, A, S, out, 4);
    cudaEventRecord(evA1, s2);

    cudaStreamWaitEvent(0, evA0, 0);
    gemm_kernel<<<dim3(32, 8, 4), 256, GEMM_SMEM>>>(0);
    cudaStreamWaitEvent(0, evA1, 0);       // joins s2 back into main
    gemm_kernel<<<dim3(32, 8, 4), 256, GEMM_SMEM>>>(4);

    bn_finalize_kernel<<<PC, 256>>>();
    synth_kernel<<<P_ * B_ * C_ * (LS / 8) / 256, 256>>>(S, gamma, beta, out);
}

// round 16
// speedup vs baseline: 1.1494x; 1.0148x over previous
#include <cuda_runtime.h>
#include <cuda_fp16.h>
#include <cstdint>

#define P_  8
#define B_  8
#define C_  128
#define L_  8192
#define PC  1024          // P*C
#define LS  4096          // L/2

// ---------------------------------------------------------------------------
// Static device scratch (no runtime allocation allowed)
// ---------------------------------------------------------------------------
__device__ __align__(16) __half g_W16[PC * PC];                   //  2 MB  W (fp16)
__device__ __align__(16) __half g_X  [(long)B_ * PC * LS];        // 64 MB  sc [b][j][l] fp16 (K-major)
__device__ __align__(16) __half g_y16[(long)B_ * PC * LS];        // 64 MB  y  [b][j][l] fp16
__device__ float g_pS[PC * 256];   // per-channel partial sums   [j][slot]
__device__ float g_pQ[PC * 256];   // per-channel partial sumsq  [j][slot]
__device__ float g_mean[PC];
__device__ float g_rstd[PC];

__device__ __forceinline__ uint32_t smem_u32(const void* p) {
    uint32_t a;
    asm("{ .reg .u64 t; cvta.to.shared.u64 t, %1; cvt.u32.u64 %0, t; }" : "=r"(a) : "l"(p));
    return a;
}

#define CP_ASYNC16(saddr, gptr) \
    asm volatile("cp.async.cg.shared.global [%0], [%1], 16;" :: "r"(saddr), "l"(gptr))
#define CP_COMMIT() asm volatile("cp.async.commit_group;")
#define CP_WAIT1()  asm volatile("cp.async.wait_group 1;")

#define LDSM4(r0, r1, r2, r3, addr) \
    asm volatile("ldmatrix.sync.aligned.m8n8.x4.shared.b16 {%0,%1,%2,%3}, [%4];" \
        : "=r"(r0), "=r"(r1), "=r"(r2), "=r"(r3) : "r"(addr))

#define LDSM4T(r0, r1, r2, r3, addr) \
    asm volatile("ldmatrix.sync.aligned.m8n8.x4.trans.shared.b16 {%0,%1,%2,%3}, [%4];" \
        : "=r"(r0), "=r"(r1), "=r"(r2), "=r"(r3) : "r"(addr))

#define MMA16816(acc, a, b) \
    asm volatile("mma.sync.aligned.m16n8k16.row.col.f32.f16.f16.f32 " \
        "{%0,%1,%2,%3}, {%4,%5,%6,%7}, {%8,%9}, {%0,%1,%2,%3};" \
        : "+f"((acc)[0]), "+f"((acc)[1]), "+f"((acc)[2]), "+f"((acc)[3]) \
        : "r"((a)[0]), "r"((a)[1]), "r"((a)[2]), "r"((a)[3]), \
          "r"((b)[0]), "r"((b)[1]))

// ---------------------------------------------------------------------------
// Pass 1 (half of 4 batches): Haar analysis — PURE STREAMING, no smem.
// Writes detail-half of output and fp16 sc directly to g_X [b][j][l]
// (natural K-major layout; GEMM reads it via ldmatrix.trans).
// 4 independent LDG.128 per thread (MLP 4), all stores coalesced.
// ---------------------------------------------------------------------------
__global__ __launch_bounds__(256) void analysis_kernel(
    const float* __restrict__ xs, const float* __restrict__ A,
    const float* __restrict__ S, float* __restrict__ out, int b0)
{
    const int t  = threadIdx.x;
    const int b  = b0 + blockIdx.z;
    const int j  = blockIdx.y * 8 + (t >> 5);
    const int mb = blockIdx.x * 128 + (t & 31);    // float4-group base

    const float a00 = A[0], a01 = A[1], a10 = A[2], a11 = A[3];
    const float s00 = S[0], s01 = S[1], s10 = S[2], s11 = S[3];

    const int p = j >> 7, c = j & 127;
    const long base = ((long)((p * B_ + b) * C_ + c)) << 13;   // xs/out row (*8192)
    const long Xrow = ((long)(b * PC + j)) * LS;

    float4 x4v[4];
    #pragma unroll
    for (int i = 0; i < 4; i++)
        x4v[i] = *(const float4*)(xs + base + 4 * (mb + 32 * i));

    #pragma unroll
    for (int i = 0; i < 4; i++) {
        int m = mb + 32 * i;
        float4 x4 = x4v[i];
        float sc0 = a00 * x4.x + a01 * x4.y;
        float sc1 = a00 * x4.z + a01 * x4.w;
        float d0  = a10 * x4.x + a11 * x4.y;
        float d1  = a10 * x4.z + a11 * x4.w;
        *(float2*)(out + base + LS + 2 * m)
            = make_float2(s00 * d0 + s01 * d1, s10 * d0 + s11 * d1);
        __half2 h2;
        h2.x = __float2half(sc0);
        h2.y = __float2half(sc1);
        *(__half2*)(g_X + Xrow + 2 * m) = h2;
    }
}

// ---------------------------------------------------------------------------
// W in fp16 (full matrix)
// ---------------------------------------------------------------------------
__global__ void wsplit_kernel(const float* __restrict__ W)
{
    int i = blockIdx.x * 256 + threadIdx.x;
    g_W16[i] = __float2half(W[i]);
}

// ---------------------------------------------------------------------------
// Pass 2 (half of 4 batches): HMMA fp16 GEMM  y = W@sc (K=1024), fp32 accum.
// CTA 128x128, 256 threads (2x4 warps of 64x32), 32 K-iters BK=32, 3-stage
// cp.async pipeline, __launch_bounds__(256,2).
// B operand read K-major from g_X via ldmatrix.trans; B smem tile is
// [32 k-rows][256B], chunk-swizzled c^(row&7) (conflict-free both ways).
// Epilogue: y16 = acc, BN partials from fp32 regs.
// ---------------------------------------------------------------------------
#define STAGE_B 16384          // A 8KB | B 8KB
#define GEMM_SMEM 49152        // 3 stages; epilogue reuses first 4KB

__device__ __forceinline__ void load_stage(uint32_t sbase, int stg,
    const __half* __restrict__ Asrc,
    const __half* __restrict__ Bsrc, int kk, int t)
{
    uint32_t sa = sbase + stg * STAGE_B;
    #pragma unroll
    for (int i = 0; i < 2; i++) {                     // A: 128 m-rows x 4 chunks (64B rows)
        int idx = t + 256 * i;
        int row = idx >> 2, c = idx & 3;
        uint32_t sw = (uint32_t)((c ^ ((row >> 1) & 3)) << 4);
        CP_ASYNC16(sa + row * 64 + sw, Asrc + (long)row * PC + kk * 32 + c * 8);
    }
    #pragma unroll
    for (int i = 0; i < 2; i++) {                     // B: 32 k-rows x 16 chunks (256B rows)
        int idx = t + 256 * i;
        int row = idx >> 4, c = idx & 15;
        uint32_t sw = (uint32_t)((c ^ (row & 7)) << 4);
        CP_ASYNC16(sa + 8192 + row * 256 + sw,
                   Bsrc + ((long)(kk * 32 + row)) * LS + c * 8);
    }
}

__global__ void __launch_bounds__(256, 2) gemm_kernel(int b0)
{
    extern __shared__ char smem[];
    const uint32_t sbase = smem_u32(smem);
    const int t    = threadIdx.x;
    const int lane = t & 31;
    const int wid  = t >> 5;
    const int wm   = wid >> 2;            // 0..1  (64 m-rows each)
    const int wn   = wid & 3;             // 0..3  (32 n-cols each)
    const int n0   = blockIdx.x * 128;
    const int m0   = blockIdx.y * 128;
    const int b    = b0 + blockIdx.z;

    const __half* Asrc = g_W16 + (long)m0 * PC;
    const __half* Bsrc = g_X + (long)b * PC * LS + n0;   // row j, col l

    // A ldmatrix constants (unchanged)
    const int rA  = lane & 15;
    const int hkA = lane >> 4;
    const int cA  = (rA >> 1) & 3;
    const uint32_t offA = (uint32_t)(wm * 64 + rA) * 64;
    // B trans-ldmatrix constants: lanes 0-7: k0-7/nOct0; 8-15: k8-15/nOct0;
    // 16-23: k0-7/nOct1; 24-31: k8-15/nOct1.
    const int rBk  = (lane & 7) + ((lane >> 3) & 1) * 8;   // k-row within 16
    const int nOct = (lane >> 4) & 1;
    const int swB  = lane & 7;                             // = rBk & 7

    float acc[4][4][4];
    #pragma unroll
    for (int mi = 0; mi < 4; mi++)
        #pragma unroll
        for (int ni = 0; ni < 4; ni++)
            #pragma unroll
            for (int q = 0; q < 4; q++) acc[mi][ni][q] = 0.f;

    load_stage(sbase, 0, Asrc, Bsrc, 0, t); CP_COMMIT();
    load_stage(sbase, 1, Asrc, Bsrc, 1, t); CP_COMMIT();

    int stg = 0;
    for (int kt = 0; kt < 32; kt++) {
        CP_WAIT1();
        __syncthreads();
        {
            int kn = kt + 2;
            if (kn < 32) {
                int stn = stg + 2; if (stn >= 3) stn -= 3;
                load_stage(sbase, stn, Asrc, Bsrc, kn, t);
            }
            CP_COMMIT();
        }
        uint32_t sa = sbase + stg * STAGE_B;
        #pragma unroll
        for (int s2 = 0; s2 < 2; s2++) {
            uint32_t bf[4][2];
            #pragma unroll
            for (int p = 0; p < 2; p++) {
                int chunk = wn * 4 + p * 2 + nOct;         // 16B chunk index
                uint32_t addr = sa + 8192u
                              + (uint32_t)(s2 * 16 + rBk) * 256
                              + (uint32_t)((chunk ^ swB) << 4);
                LDSM4T(bf[2 * p][0], bf[2 * p][1], bf[2 * p + 1][0], bf[2 * p + 1][1], addr);
            }
            uint32_t a[4][4];
            #pragma unroll
            for (int mi = 0; mi < 4; mi++) {
                uint32_t addr = sa + offA + mi * (16 * 64)
                              + (uint32_t)(((2 * s2 + hkA) ^ cA) << 4);
                LDSM4(a[mi][0], a[mi][1], a[mi][2], a[mi][3], addr);
            }
            #pragma unroll
            for (int mi = 0; mi < 4; mi++)
                #pragma unroll
                for (int ni = 0; ni < 4; ni++)
                    MMA16816(acc[mi][ni], a[mi], bf[ni]);
        }
        if (++stg == 3) stg = 0;
    }

    // ---- Epilogue: y16 = acc, BN partials from fp32 regs ----
    __syncthreads();                       // pipeline stages -> scratch
    float* sS = (float*)smem;              // [128][4]
    float* sQ = (float*)smem + 512;

    const int rl = wm * 64 + (lane >> 2);  // local m-row base
    const int c0 = n0 + wn * 32 + (lane & 3) * 2;
    #pragma unroll
    for (int mi = 0; mi < 4; mi++) {
        int rla = rl + mi * 16, rlb = rla + 8;
        long oa = ((long)b * PC + m0 + rla) * LS + c0;
        long ob = ((long)b * PC + m0 + rlb) * LS + c0;
        float sa_ = 0.f, qa_ = 0.f, sb_ = 0.f, qb_ = 0.f;
        #pragma unroll
        for (int ni = 0; ni < 4; ni++) {
            float y0 = acc[mi][ni][0], y1 = acc[mi][ni][1];
            float y2 = acc[mi][ni][2], y3 = acc[mi][ni][3];
            *(__half2*)(g_y16 + oa + ni * 8) = __floats2half2_rn(y0, y1);
            *(__half2*)(g_y16 + ob + ni * 8) = __floats2half2_rn(y2, y3);
            sa_ += y0 + y1; qa_ += y0 * y0 + y1 * y1;
            sb_ += y2 + y3; qb_ += y2 * y2 + y3 * y3;
        }
        sa_ += __shfl_xor_sync(0xffffffffu, sa_, 1);
        sa_ += __shfl_xor_sync(0xffffffffu, sa_, 2);
        qa_ += __shfl_xor_sync(0xffffffffu, qa_, 1);
        qa_ += __shfl_xor_sync(0xffffffffu, qa_, 2);
        sb_ += __shfl_xor_sync(0xffffffffu, sb_, 1);
        sb_ += __shfl_xor_sync(0xffffffffu, sb_, 2);
        qb_ += __shfl_xor_sync(0xffffffffu, qb_, 1);
        qb_ += __shfl_xor_sync(0xffffffffu, qb_, 2);
        if ((lane & 3) == 0) {
            sS[rla * 4 + wn] = sa_; sQ[rla * 4 + wn] = qa_;
            sS[rlb * 4 + wn] = sb_; sQ[rlb * 4 + wn] = qb_;
        }
    }
    __syncthreads();
    if (t < 128) {
        float s = sS[t * 4] + sS[t * 4 + 1] + sS[t * 4 + 2] + sS[t * 4 + 3];
        float q = sQ[t * 4] + sQ[t * 4 + 1] + sQ[t * 4 + 2] + sQ[t * 4 + 3];
        int slot = b * 32 + blockIdx.x;    // 256 slots per channel
        g_pS[(m0 + t) * 256 + slot] = s;
        g_pQ[(m0 + t) * 256 + slot] = q;
    }
}

// ---------------------------------------------------------------------------
// Pass 3: BN finalize — reduce 256 deterministic partials per channel.
// ---------------------------------------------------------------------------
__global__ void bn_finalize_kernel()
{
    int j = blockIdx.x;
    int t = threadIdx.x;                   // 256 threads
    float s = g_pS[j * 256 + t];
    float q = g_pQ[j * 256 + t];
    #pragma unroll
    for (int o = 16; o > 0; o >>= 1) {
        s += __shfl_down_sync(0xffffffffu, s, o);
        q += __shfl_down_sync(0xffffffffu, q, o);
    }
    __shared__ float ss[8], sq[8];
    int w = t >> 5;
    if ((t & 31) == 0) { ss[w] = s; sq[w] = q; }
    __syncthreads();
    if (t == 0) {
        float S = 0.f, Q = 0.f;
        #pragma unroll
        for (int i = 0; i < 8; i++) { S += ss[i]; Q += sq[i]; }
        const float inv = 1.f / (float)(B_ * LS);
        float mean = S * inv;
        float var  = Q * inv - mean * mean;
        g_mean[j] = mean;
        g_rstd[j] = rsqrtf(var + 1e-5f);
    }
}

// ---------------------------------------------------------------------------
// Pass 4: BN + exact GELU + Haar synthesis -> FIRST half of the output.
// ---------------------------------------------------------------------------
__device__ __forceinline__ float gelu_exact(float z)
{
    return 0.5f * z * (1.0f + erff(z * 0.70710678118654752440f));
}

__global__ __launch_bounds__(256) void synth_kernel(
    const float* __restrict__ S,
    const float* __restrict__ gamma,
    const float* __restrict__ beta,
    float* __restrict__ out)
{
    int tid = blockIdx.x * blockDim.x + threadIdx.x;   // < P*B*C*512
    int m8 = tid & 511;                  // group of 8 l-values
    int c  = (tid >> 9) & 127;
    int b  = (tid >> 16) & 7;
    int p  = tid >> 19;

    int j = p * C_ + c;
    const __half2* yp = (const __half2*)(g_y16 + ((long)(b * PC + j)) * LS + 8 * m8);
    uint4 raw = *(const uint4*)yp;
    float2 v0 = __half22float2(*(const __half2*)&raw.x);
    float2 v1 = __half22float2(*(const __half2*)&raw.y);
    float2 v2 = __half22float2(*(const __half2*)&raw.z);
    float2 v3 = __half22float2(*(const __half2*)&raw.w);

    float mean = g_mean[j], rstd = g_rstd[j];
    float gm = gamma[j] * rstd;
    float bo = beta[j] - mean * gm;
    float s00 = S[0], s01 = S[1], s10 = S[2], s11 = S[3];

    float a0 = gelu_exact(v0.x * gm + bo);
    float a1 = gelu_exact(v0.y * gm + bo);
    float a2 = gelu_exact(v1.x * gm + bo);
    float a3 = gelu_exact(v1.y * gm + bo);
    float a4 = gelu_exact(v2.x * gm + bo);
    float a5 = gelu_exact(v2.y * gm + bo);
    float a6 = gelu_exact(v3.x * gm + bo);
    float a7 = gelu_exact(v3.y * gm + bo);

    float4 o0 = make_float4(s00 * a0 + s01 * a1, s10 * a0 + s11 * a1,
                            s00 * a2 + s01 * a3, s10 * a2 + s11 * a3);
    float4 o1 = make_float4(s00 * a4 + s01 * a5, s10 * a4 + s11 * a5,
                            s00 * a6 + s01 * a7, s10 * a6 + s11 * a7);

    float* op = out + (((long)((p * B_ + b) * C_ + c)) << 13) + 8 * m8;
    *(float4*)op       = o0;
    *(float4*)(op + 4) = o1;
}

// ---------------------------------------------------------------------------
// Launch: two-half overlap — analysis halves on side stream; GEMM halves on
// main stream gated by events. A1 overlaps G0.
// ---------------------------------------------------------------------------
extern "C" void kernel_launch(void* const* d_in, const int* in_sizes, int n_in,
                              void* d_out, int out_size)
{
    const float* xs    = (const float*)d_in[0];
    const float* A     = (const float*)d_in[1];
    const float* S     = (const float*)d_in[2];
    const float* W     = (const float*)d_in[3];
    const float* gamma = (const float*)d_in[4];
    const float* beta  = (const float*)d_in[5];
    float* out = (float*)d_out;

    static int inited = 0;
    static cudaStream_t s2;
    static cudaEvent_t ev0, evA0, evA1;
    if (!inited) {
        cudaFuncSetAttribute(gemm_kernel,
                             cudaFuncAttributeMaxDynamicSharedMemorySize, GEMM_SMEM);
        cudaStreamCreateWithFlags(&s2, cudaStreamNonBlocking);
        cudaEventCreateWithFlags(&ev0,  cudaEventDisableTiming);
        cudaEventCreateWithFlags(&evA0, cudaEventDisableTiming);
        cudaEventCreateWithFlags(&evA1, cudaEventDisableTiming);
        inited = 1;
    }

    cudaEventRecord(ev0, 0);
    cudaStreamWaitEvent(s2, ev0, 0);

    wsplit_kernel<<<PC * PC / 256, 256>>>(W);

    analysis_kernel<<<dim3(16, 128, 4), 256, 0, s2>>>(xs, A, S, out, 0);
    cudaEventRecord(evA0, s2);
    analysis_kernel<<<dim3(16, 128, 4), 256, 0, s2>>>(xs, A, S, out, 4);
    cudaEventRecord(evA1, s2);

    cudaStreamWaitEvent(0, evA0, 0);
    gemm_kernel<<<dim3(32, 8, 4), 256, GEMM_SMEM>>>(0);
    cudaStreamWaitEvent(0, evA1, 0);       // joins s2 back into main
    gemm_kernel<<<dim3(32, 8, 4), 256, GEMM_SMEM>>>(4);

    bn_finalize_kernel<<<PC, 256>>>();
    synth_kernel<<<P_ * B_ * C_ * (LS / 8) / 256, 256>>>(S, gamma, beta, out);
}